// round 1
// baseline (speedup 1.0000x reference)
#include <cuda_runtime.h>

#define B_  2
#define S_  2048
#define D_  1024
#define H_  16
#define HD_ 64
#define M_  (B_ * S_)          // 4096 rows

#define WIN_TILES 6            // 384-key decay window: 0.95^384 ~ 3e-9
#define TBL_N ((WIN_TILES + 1) * 64)   // 448

// ---------------- scratch (device globals: no allocation allowed) ----------
__device__ float  g_q[M_ * D_];
__device__ float  g_k[M_ * D_];
__device__ float  g_v[M_ * D_];
__device__ float  g_attn[M_ * D_];
__device__ float  g_proj[M_ * D_];
__device__ float2 g_part[32 * 32];
__device__ float2 g_stats[32];

// ---------------- 128x128x16 double-buffered SGEMM body --------------------
__device__ __forceinline__ void gemm128(
    const float* __restrict__ A,   // [M_, 1024]
    const float* __restrict__ W,   // [1024, 1024]
    const float* __restrict__ bias,
    float* __restrict__ C)
{
    const int K = D_, N = D_;
    __shared__ float As[2][16][128];   // [k][m] (transposed on store)
    __shared__ float Bs[2][16][128];   // [k][n]

    const int tid = threadIdx.x;
    const int tx = tid & 15, ty = tid >> 4;
    const int m0 = blockIdx.y << 7;
    const int n0 = blockIdx.x << 7;

    const int aRow = tid >> 2;         // 0..63
    const int aCol = (tid & 3) << 2;   // 0,4,8,12
    const int bRow = tid >> 5;         // 0..7
    const int bCol = (tid & 31) << 2;  // 0..124

    // prologue: tile 0
    {
#pragma unroll
        for (int r = 0; r < 2; r++) {
            float4 av = *(const float4*)(A + (m0 + aRow + r * 64) * K + aCol);
            As[0][aCol + 0][aRow + r * 64] = av.x;
            As[0][aCol + 1][aRow + r * 64] = av.y;
            As[0][aCol + 2][aRow + r * 64] = av.z;
            As[0][aCol + 3][aRow + r * 64] = av.w;
            *(float4*)(&Bs[0][bRow + r * 8][bCol]) =
                *(const float4*)(W + (bRow + r * 8) * N + n0 + bCol);
        }
    }
    __syncthreads();

    float acc[8][8];
#pragma unroll
    for (int i = 0; i < 8; i++)
#pragma unroll
        for (int j = 0; j < 8; j++) acc[i][j] = 0.f;

    const int nT = K / 16;   // 64
    for (int t = 0; t < nT; t++) {
        const int buf = t & 1;
        float4 apre[2], bpre[2];
        if (t + 1 < nT) {
            const int kk = (t + 1) << 4;
#pragma unroll
            for (int r = 0; r < 2; r++) {
                apre[r] = *(const float4*)(A + (m0 + aRow + r * 64) * K + kk + aCol);
                bpre[r] = *(const float4*)(W + (kk + bRow + r * 8) * N + n0 + bCol);
            }
        }
#pragma unroll
        for (int k = 0; k < 16; k++) {
            float4 a0 = *(const float4*)(&As[buf][k][ty * 8]);
            float4 a1 = *(const float4*)(&As[buf][k][ty * 8 + 4]);
            float4 b0 = *(const float4*)(&Bs[buf][k][tx * 8]);
            float4 b1 = *(const float4*)(&Bs[buf][k][tx * 8 + 4]);
            float aa[8] = {a0.x, a0.y, a0.z, a0.w, a1.x, a1.y, a1.z, a1.w};
            float bb[8] = {b0.x, b0.y, b0.z, b0.w, b1.x, b1.y, b1.z, b1.w};
#pragma unroll
            for (int i = 0; i < 8; i++)
#pragma unroll
                for (int j = 0; j < 8; j++)
                    acc[i][j] = fmaf(aa[i], bb[j], acc[i][j]);
        }
        if (t + 1 < nT) {
            const int nb = buf ^ 1;
#pragma unroll
            for (int r = 0; r < 2; r++) {
                As[nb][aCol + 0][aRow + r * 64] = apre[r].x;
                As[nb][aCol + 1][aRow + r * 64] = apre[r].y;
                As[nb][aCol + 2][aRow + r * 64] = apre[r].z;
                As[nb][aCol + 3][aRow + r * 64] = apre[r].w;
                *(float4*)(&Bs[nb][bRow + r * 8][bCol]) = bpre[r];
            }
            __syncthreads();
        }
    }

#pragma unroll
    for (int i = 0; i < 8; i++) {
        const int row = m0 + ty * 8 + i;
#pragma unroll
        for (int j = 0; j < 8; j += 4) {
            const int col = n0 + tx * 8 + j;
            float4 o;
            o.x = acc[i][j + 0] + bias[col + 0];
            o.y = acc[i][j + 1] + bias[col + 1];
            o.z = acc[i][j + 2] + bias[col + 2];
            o.w = acc[i][j + 3] + bias[col + 3];
            *(float4*)(C + (size_t)row * N + col) = o;
        }
    }
}

__global__ __launch_bounds__(256) void qkv_kernel(
    const float* __restrict__ x,
    const float* __restrict__ Wq, const float* __restrict__ bq,
    const float* __restrict__ Wk, const float* __restrict__ bk,
    const float* __restrict__ Wv, const float* __restrict__ bv)
{
    const float* W; const float* b; float* out;
    if (blockIdx.z == 0)      { W = Wq; b = bq; out = g_q; }
    else if (blockIdx.z == 1) { W = Wk; b = bk; out = g_k; }
    else                      { W = Wv; b = bv; out = g_v; }
    gemm128(x, W, b, out);
}

__global__ __launch_bounds__(256) void proj_kernel(
    const float* __restrict__ Wo, const float* __restrict__ bo)
{
    gemm128(g_attn, Wo, bo, g_proj);
}

// ---------------- windowed decay attention ---------------------------------
struct AttnSmem {
    float Qs[64][65];
    float Ks[64][65];
    float Vs[64][65];
    float Ss[64][65];
    float tbl[TBL_N];
};

extern __shared__ unsigned char sm_raw[];

__global__ __launch_bounds__(256) void attn_kernel()
{
    AttnSmem* sm = (AttnSmem*)sm_raw;
    const int tid = threadIdx.x;
    const int qt = blockIdx.x;            // 0..31 query tile
    const int bh = blockIdx.y;            // 0..31
    const int b = bh >> 4, h = bh & 15;

    // decay^d table, d in [0, 448)
    for (int d = tid; d < TBL_N; d += 256)
        sm->tbl[d] = exp2f((float)d * -0.07400058144377693f);

    const int lrow = tid >> 4;            // 0..15
    const int lcol = (tid & 15) << 2;     // 0..60

    const float* qg = g_q + ((b * S_ + (qt << 6)) * D_) + (h << 6);
#pragma unroll
    for (int r = 0; r < 4; r++) {
        const int row = lrow + (r << 4);
        float4 v = *(const float4*)(qg + row * D_ + lcol);
        sm->Qs[row][lcol + 0] = v.x;
        sm->Qs[row][lcol + 1] = v.y;
        sm->Qs[row][lcol + 2] = v.z;
        sm->Qs[row][lcol + 3] = v.w;
    }

    const int tx = tid & 15, ty = tid >> 4;
    float O[4][4];
#pragma unroll
    for (int i = 0; i < 4; i++)
#pragma unroll
        for (int j = 0; j < 4; j++) O[i][j] = 0.f;

    int jt0 = qt - WIN_TILES; if (jt0 < 0) jt0 = 0;
    __syncthreads();

    for (int jt = jt0; jt <= qt; jt++) {
        const float* kg = g_k + ((b * S_ + (jt << 6)) * D_) + (h << 6);
        const float* vg = g_v + ((b * S_ + (jt << 6)) * D_) + (h << 6);
#pragma unroll
        for (int r = 0; r < 4; r++) {
            const int row = lrow + (r << 4);
            float4 kv4 = *(const float4*)(kg + row * D_ + lcol);
            sm->Ks[row][lcol + 0] = kv4.x;
            sm->Ks[row][lcol + 1] = kv4.y;
            sm->Ks[row][lcol + 2] = kv4.z;
            sm->Ks[row][lcol + 3] = kv4.w;
            float4 vv4 = *(const float4*)(vg + row * D_ + lcol);
            sm->Vs[row][lcol + 0] = vv4.x;
            sm->Vs[row][lcol + 1] = vv4.y;
            sm->Vs[row][lcol + 2] = vv4.z;
            sm->Vs[row][lcol + 3] = vv4.w;
        }
        __syncthreads();

        // S = Q K^T  (thread tile: rows ty*4+i, cols tx+16j — conflict-free)
        float s[4][4];
#pragma unroll
        for (int i = 0; i < 4; i++)
#pragma unroll
            for (int j = 0; j < 4; j++) s[i][j] = 0.f;

#pragma unroll 8
        for (int d = 0; d < 64; d++) {
            float qv[4], kv[4];
#pragma unroll
            for (int i = 0; i < 4; i++) qv[i] = sm->Qs[ty * 4 + i][d];
#pragma unroll
            for (int j = 0; j < 4; j++) kv[j] = sm->Ks[tx + 16 * j][d];
#pragma unroll
            for (int i = 0; i < 4; i++)
#pragma unroll
                for (int j = 0; j < 4; j++)
                    s[i][j] = fmaf(qv[i], kv[j], s[i][j]);
        }

        // apply decay mask, stage S to smem
        const int dbase = ((qt - jt) << 6) + ty * 4 - tx;
#pragma unroll
        for (int i = 0; i < 4; i++)
#pragma unroll
            for (int j = 0; j < 4; j++) {
                const int diff = dbase + i - 16 * j;
                const float f = (diff >= 0) ? sm->tbl[diff] : 0.f;
                sm->Ss[ty * 4 + i][tx + 16 * j] = s[i][j] * f;
            }
        __syncthreads();

        // O += S V  (thread tile: rows ty*4+i, cols d = tx+16j)
#pragma unroll 8
        for (int kk = 0; kk < 64; kk++) {
            float sv[4], vv[4];
#pragma unroll
            for (int i = 0; i < 4; i++) sv[i] = sm->Ss[ty * 4 + i][kk];
#pragma unroll
            for (int j = 0; j < 4; j++) vv[j] = sm->Vs[kk][tx + 16 * j];
#pragma unroll
            for (int i = 0; i < 4; i++)
#pragma unroll
                for (int j = 0; j < 4; j++)
                    O[i][j] = fmaf(sv[i], vv[j], O[i][j]);
        }
        __syncthreads();
    }

    float* og = g_attn + ((b * S_ + (qt << 6)) * D_) + (h << 6);
#pragma unroll
    for (int i = 0; i < 4; i++)
#pragma unroll
        for (int j = 0; j < 4; j++)
            og[(ty * 4 + i) * D_ + tx + 16 * j] = O[i][j];
}

// ---------------- GroupNorm (groups = (b,h), reduce over S x hd) -----------
__global__ __launch_bounds__(256) void gn_partial()
{
    const int c = blockIdx.x;   // 0..31 seq chunk (64 rows)
    const int g = blockIdx.y;   // 0..31 group
    const int b = g >> 4, h = g & 15;
    const float* base = g_proj + ((b * S_ + (c << 6)) * D_) + (h << 6);
    const int lrow = threadIdx.x >> 4;
    const int lcol = (threadIdx.x & 15) << 2;

    float sum = 0.f, sq = 0.f;
#pragma unroll
    for (int r = 0; r < 4; r++) {
        float4 v = *(const float4*)(base + (lrow + (r << 4)) * D_ + lcol);
        sum += v.x + v.y + v.z + v.w;
        sq  += v.x * v.x + v.y * v.y + v.z * v.z + v.w * v.w;
    }
#pragma unroll
    for (int o = 16; o; o >>= 1) {
        sum += __shfl_down_sync(0xffffffffu, sum, o);
        sq  += __shfl_down_sync(0xffffffffu, sq,  o);
    }
    __shared__ float wsum[8], wsq[8];
    const int wid = threadIdx.x >> 5, lid = threadIdx.x & 31;
    if (lid == 0) { wsum[wid] = sum; wsq[wid] = sq; }
    __syncthreads();
    if (threadIdx.x == 0) {
        float ts = 0.f, tq = 0.f;
#pragma unroll
        for (int w = 0; w < 8; w++) { ts += wsum[w]; tq += wsq[w]; }
        g_part[g * 32 + c] = make_float2(ts, tq);
    }
}

__global__ void gn_stats()
{
    const int g = threadIdx.x;   // 32 threads
    float s = 0.f, q = 0.f;
    for (int c = 0; c < 32; c++) {
        float2 p = g_part[g * 32 + c];
        s += p.x; q += p.y;
    }
    const float n = (float)(S_ * HD_);
    const float mu = s / n;
    const float var = q / n - mu * mu;
    g_stats[g] = make_float2(mu, rsqrtf(var + 1e-5f));
}

__global__ __launch_bounds__(256) void gn_apply(
    const float* __restrict__ gamma, const float* __restrict__ beta,
    float* __restrict__ out)
{
    const int t = blockIdx.x * 256 + threadIdx.x;
    const int base = t << 2;                 // element index (x4 vectorized)
    const int d = base & (D_ - 1);
    const int row = base >> 10;
    const int b = row >> 11;                 // row / 2048
    const float2 st = g_stats[(b << 4) | (d >> 6)];
    const float4 v  = *(const float4*)(g_proj + base);
    const float4 gm = *(const float4*)(gamma + d);
    const float4 bt = *(const float4*)(beta + d);
    float4 o;
    o.x = (v.x - st.x) * st.y * gm.x + bt.x;
    o.y = (v.y - st.x) * st.y * gm.y + bt.y;
    o.z = (v.z - st.x) * st.y * gm.z + bt.z;
    o.w = (v.w - st.x) * st.y * gm.w + bt.w;
    *(float4*)(out + base) = o;
}

// ---------------- launch ----------------------------------------------------
extern "C" void kernel_launch(void* const* d_in, const int* in_sizes, int n_in,
                              void* d_out, int out_size)
{
    (void)in_sizes; (void)n_in; (void)out_size;
    const float* x     = (const float*)d_in[0];
    const float* Wq    = (const float*)d_in[1];
    const float* bq    = (const float*)d_in[2];
    const float* Wk    = (const float*)d_in[3];
    const float* bk    = (const float*)d_in[4];
    const float* Wv    = (const float*)d_in[5];
    const float* bv    = (const float*)d_in[6];
    const float* Wo    = (const float*)d_in[7];
    const float* bo    = (const float*)d_in[8];
    const float* gamma = (const float*)d_in[9];
    const float* beta  = (const float*)d_in[10];
    float* out = (float*)d_out;

    cudaFuncSetAttribute(attn_kernel,
                         cudaFuncAttributeMaxDynamicSharedMemorySize,
                         (int)sizeof(AttnSmem));

    qkv_kernel<<<dim3(8, 32, 3), 256>>>(x, Wq, bq, Wk, bk, Wv, bv);
    attn_kernel<<<dim3(32, 32), 256, sizeof(AttnSmem)>>>();
    proj_kernel<<<dim3(8, 32, 1), 256>>>(Wo, bo);
    gn_partial<<<dim3(32, 32), 256>>>();
    gn_stats<<<1, 32>>>();
    gn_apply<<<(M_ * D_) / (256 * 4), 256>>>(gamma, beta, out);
}

// round 3
// speedup vs baseline: 3.0221x; 3.0221x over previous
#include <cuda_runtime.h>
#include <cuda_bf16.h>
#include <cstdint>

#define B_  2
#define S_  2048
#define D_  1024
#define H_  16
#define HD_ 64
#define M_  (B_ * S_)          // 4096 rows

#define WIN_TILES 6            // 384-key decay window: 0.95^384 ~ 3e-9
#define TBL_N ((WIN_TILES + 1) * 64)   // 448

// ---------------- scratch (device globals: no allocation allowed) ----------
__device__ float  g_q[M_ * D_];
__device__ float  g_k[M_ * D_];
__device__ float  g_v[M_ * D_];
__device__ float  g_attn[M_ * D_];
__device__ float  g_proj[M_ * D_];
__device__ float2 g_part[32 * 32];
__device__ float2 g_stats[32];

// bf16 split operands
__device__ __align__(128) __nv_bfloat16 g_xhi[M_ * D_];
__device__ __align__(128) __nv_bfloat16 g_xlo[M_ * D_];
__device__ __align__(128) __nv_bfloat16 g_ahi[M_ * D_];
__device__ __align__(128) __nv_bfloat16 g_alo[M_ * D_];
__device__ __align__(128) __nv_bfloat16 g_wthi[4][D_ * D_];   // W^T [n][k]
__device__ __align__(128) __nv_bfloat16 g_wtlo[4][D_ * D_];

extern __shared__ unsigned char sm_raw[];

// ---------------- PTX helpers ----------------------------------------------
__device__ __forceinline__ unsigned smem_u32(const void* p) {
    unsigned r;
    asm("{ .reg .u64 t; cvta.to.shared.u64 t, %1; cvt.u32.u64 %0, t; }"
        : "=r"(r) : "l"(p));
    return r;
}

#define MBARRIER_INIT(addr, cnt) \
    asm volatile("mbarrier.init.shared.b64 [%0], %1;" :: "r"(addr), "r"(cnt) : "memory")

#define MBARRIER_WAIT_PARITY(addr, ph) do {                                     \
    unsigned _m = (addr), _p = (ph), _d;                                        \
    asm volatile("{\n\t.reg .pred p;\n\t"                                       \
        "mbarrier.try_wait.parity.acquire.cta.shared::cta.b64 p, [%1], %2;\n\t" \
        "selp.b32 %0, 1, 0, p;\n\t}"                                            \
        : "=r"(_d) : "r"(_m), "r"(_p) : "memory");                              \
    if (!_d) {                                                                  \
        asm volatile("{\n\t.reg .pred P1;\n\t"                                  \
            "WL_%=:\n\t"                                                        \
            "mbarrier.try_wait.parity.acquire.cta.shared::cta.b64 P1, [%0], %1, 0x989680;\n\t" \
            "@P1 bra.uni WD_%=;\n\t"                                            \
            "bra.uni WL_%=;\n\t"                                                \
            "WD_%=:\n\t}"                                                       \
            :: "r"(_m), "r"(_p) : "memory");                                    \
    }                                                                           \
} while (0)

#define CP_ASYNC16(dst, src) \
    asm volatile("cp.async.cg.shared.global [%0], [%1], 16;" :: "r"(dst), "l"(src))
#define CP_COMMIT() asm volatile("cp.async.commit_group;" ::: "memory")
#define CP_WAIT0()  asm volatile("cp.async.wait_group 0;" ::: "memory")
#define FENCE_PROXY_ASYNC() asm volatile("fence.proxy.async.shared::cta;" ::: "memory")
#define BAR1_160() asm volatile("bar.sync 1, 160;" ::: "memory")

#define SWZ(o) ((o) ^ (((o) >> 3) & 0x70))

#if defined(__CUDA_ARCH_FEAT_SM103_ALL)

#define TCGEN05_ALLOC(saddr, n) \
    asm volatile("tcgen05.alloc.cta_group::1.sync.aligned.shared::cta.b32 [%0], %1;" \
                 :: "r"(saddr), "r"(n) : "memory")
#define TCGEN05_DEALLOC(t, n) \
    asm volatile("tcgen05.dealloc.cta_group::1.sync.aligned.b32 %0, %1;" :: "r"(t), "r"(n))
#define TCGEN05_RELINQ() \
    asm volatile("tcgen05.relinquish_alloc_permit.cta_group::1.sync.aligned;")
#define TCGEN05_COMMIT(bar) \
    asm volatile("tcgen05.commit.cta_group::1.mbarrier::arrive::one.shared::cluster.b64 [%0];" \
                 :: "r"(bar) : "memory")
#define TCGEN05_FENCE_AFTER() \
    asm volatile("tcgen05.fence::after_thread_sync;" ::: "memory")
#define TCGEN05_FENCE_BEFORE() \
    asm volatile("tcgen05.fence::before_thread_sync;" ::: "memory")
#define TCGEN05_WAIT_LD() \
    asm volatile("tcgen05.wait::ld.sync.aligned;" ::: "memory")

#define TCGEN05_LD_32X32B_X32(r, tmem_addr) \
    asm volatile( \
        "tcgen05.ld.sync.aligned.32x32b.x32.b32 " \
        "{%0, %1, %2, %3, %4, %5, %6, %7, " \
        " %8, %9, %10, %11, %12, %13, %14, %15, " \
        " %16, %17, %18, %19, %20, %21, %22, %23, " \
        " %24, %25, %26, %27, %28, %29, %30, %31}, [%32];" \
        : "=r"((r)[0]),  "=r"((r)[1]),  "=r"((r)[2]),  "=r"((r)[3]), \
          "=r"((r)[4]),  "=r"((r)[5]),  "=r"((r)[6]),  "=r"((r)[7]), \
          "=r"((r)[8]),  "=r"((r)[9]),  "=r"((r)[10]), "=r"((r)[11]), \
          "=r"((r)[12]), "=r"((r)[13]), "=r"((r)[14]), "=r"((r)[15]), \
          "=r"((r)[16]), "=r"((r)[17]), "=r"((r)[18]), "=r"((r)[19]), \
          "=r"((r)[20]), "=r"((r)[21]), "=r"((r)[22]), "=r"((r)[23]), \
          "=r"((r)[24]), "=r"((r)[25]), "=r"((r)[26]), "=r"((r)[27]), \
          "=r"((r)[28]), "=r"((r)[29]), "=r"((r)[30]), "=r"((r)[31]) \
        : "r"(tmem_addr))

__device__ __forceinline__ void mma_f16_ss(
    unsigned d_tmem, unsigned long long a_desc, unsigned long long b_desc,
    unsigned idesc, unsigned enable)
{
    asm volatile(
        "{\n\t.reg .pred p;\n\t"
        "setp.ne.u32 p, %4, 0;\n\t"
        "tcgen05.mma.cta_group::1.kind::f16 [%0], %1, %2, %3, {%5, %5, %5, %5}, p;\n\t"
        "}"
        :: "r"(d_tmem), "l"(a_desc), "l"(b_desc), "r"(idesc), "r"(enable), "r"(0u)
        : "memory");
}

__device__ __forceinline__ unsigned long long sdesc(unsigned addr) {
    // SW128, Blackwell version=1, LBO=1, SBO=64
    return 0x4000404000010000ull | ((unsigned long long)(addr >> 4) & 0x3FFF);
}

#endif  // __CUDA_ARCH_FEAT_SM103_ALL

// ---------------- tcgen05 split-bf16 GEMM: C[4096x1024] = A*W^T + bias -----
// tile 128(M) x 256(N), K chunk 64, 2 stages, 160 threads.
#define GEMM_IDESC 0x08400490u   // F32 acc, bf16 a/b, N=256, M=128
#define STAGE_BYTES 98304
#define DYN_SMEM (2048 + 2 * STAGE_BYTES)

// smem map: [0]empty0 [8]empty1 [16]mma_done [64]tmem_ptr [1024]bias[256] [2048+]tiles
__device__ __forceinline__ void load_tile(
    unsigned dst_base, const __nv_bfloat16* gsrc, int row0, int kb, int nrows, int t)
{
    const char* src0 = (const char*)gsrc + ((size_t)row0 * D_ + kb) * 2;
    const int ng = nrows * 8;
    for (int g = t; g < ng; g += 128) {
        const int row = g >> 3, c = g & 7;
        unsigned dst = dst_base + SWZ(row * 128 + c * 16);
        CP_ASYNC16(dst, src0 + (size_t)row * (D_ * 2) + c * 16);
    }
}

__global__ __launch_bounds__(160, 1) void gemm_tc(
    int mode,
    const float* __restrict__ bq, const float* __restrict__ bk,
    const float* __restrict__ bv, const float* __restrict__ bo)
{
    const int tid = threadIdx.x;
    const int n0 = blockIdx.x << 8;     // 0..768
    const int m0 = blockIdx.y << 7;     // 0..3968
    const int z = blockIdx.z;

    const __nv_bfloat16 *Ahi, *Alo, *Bhi, *Blo;
    const float* bias;
    float* C;
    if (mode == 0) {
        Ahi = g_xhi; Alo = g_xlo;
        Bhi = g_wthi[z]; Blo = g_wtlo[z];
        bias = (z == 0) ? bq : (z == 1) ? bk : bv;
        C = (z == 0) ? g_q : (z == 1) ? g_k : g_v;
    } else {
        Ahi = g_ahi; Alo = g_alo;
        Bhi = g_wthi[3]; Blo = g_wtlo[3];
        bias = bo; C = g_proj;
    }

#if defined(__CUDA_ARCH_FEAT_SM103_ALL)
    const unsigned sb = smem_u32(sm_raw);
    const int warp = tid >> 5, lane = tid & 31;

    if (tid == 0) {
        MBARRIER_INIT(sb + 0, 1);
        MBARRIER_INIT(sb + 8, 1);
        MBARRIER_INIT(sb + 16, 1);
    }
    if (warp == 4) {
        TCGEN05_ALLOC(sb + 64, 256);
        TCGEN05_RELINQ();
    }
    if (tid < 128) {
        float* sbias = (float*)(sm_raw + 1024);
        sbias[tid] = bias[n0 + tid];
        sbias[tid + 128] = bias[n0 + 128 + tid];
    }
    __syncthreads();

    unsigned tmem;
    asm volatile("ld.shared.b32 %0, [%1];" : "=r"(tmem) : "r"(sb + 64));

    if (warp < 4) {
        // ---- producer loop ----
        for (int c = 0; c < 16; c++) {
            const int s = c & 1, u = c >> 1;
            const unsigned ph = (unsigned)((u & 1) ^ 1);
            MBARRIER_WAIT_PARITY(sb + s * 8, ph);
            const unsigned st = sb + 2048 + s * STAGE_BYTES;
            const int kb = c << 6;
            load_tile(st +     0, Ahi, m0, kb, 128, tid);
            load_tile(st + 16384, Alo, m0, kb, 128, tid);
            load_tile(st + 32768, Bhi, n0, kb, 256, tid);
            load_tile(st + 65536, Blo, n0, kb, 256, tid);
            CP_COMMIT();
            CP_WAIT0();
            FENCE_PROXY_ASYNC();
            BAR1_160();
        }
        // ---- epilogue ----
        MBARRIER_WAIT_PARITY(sb + 16, 0);
        TCGEN05_FENCE_AFTER();
        const float* sbias = (const float*)(sm_raw + 1024);
        float* crow = C + (size_t)(m0 + warp * 32 + lane) * D_ + n0;
        for (int cb = 0; cb < 8; cb++) {
            unsigned r[32];
            TCGEN05_LD_32X32B_X32(r, tmem + cb * 32);
            TCGEN05_WAIT_LD();
#pragma unroll
            for (int j = 0; j < 32; j += 4) {
                float4 o;
                o.x = __uint_as_float(r[j + 0]) + sbias[cb * 32 + j + 0];
                o.y = __uint_as_float(r[j + 1]) + sbias[cb * 32 + j + 1];
                o.z = __uint_as_float(r[j + 2]) + sbias[cb * 32 + j + 2];
                o.w = __uint_as_float(r[j + 3]) + sbias[cb * 32 + j + 3];
                *(float4*)(crow + cb * 32 + j) = o;
            }
        }
        TCGEN05_FENCE_BEFORE();
    } else {
        // ---- MMA warp ----
        for (int c = 0; c < 16; c++) {
            BAR1_160();
            if (lane == 0) {
                const int s = c & 1;
                const unsigned st = sb + 2048 + s * STAGE_BYTES;
                const unsigned long long dahi = sdesc(st);
                const unsigned long long dalo = sdesc(st + 16384);
                const unsigned long long dbhi = sdesc(st + 32768);
                const unsigned long long dblo = sdesc(st + 65536);
#pragma unroll
                for (int k = 0; k < 4; k++) {
                    const unsigned long long off = 2ull * k;
                    mma_f16_ss(tmem, dahi + off, dbhi + off, GEMM_IDESC,
                               (c == 0 && k == 0) ? 0u : 1u);
                    mma_f16_ss(tmem, dahi + off, dblo + off, GEMM_IDESC, 1u);
                    mma_f16_ss(tmem, dalo + off, dbhi + off, GEMM_IDESC, 1u);
                }
                TCGEN05_COMMIT(sb + s * 8);
            }
        }
        if (lane == 0) TCGEN05_COMMIT(sb + 16);
    }
    __syncthreads();
    if (warp == 4) TCGEN05_DEALLOC(tmem, 256);
#else
    // -------- correct (slow) fallback for non-sm_103a compilation targets ---
    for (int idx = tid; idx < 128 * 256; idx += 160) {
        const int i = idx >> 8, j = idx & 255;
        const __nv_bfloat16* ah = Ahi + (size_t)(m0 + i) * D_;
        const __nv_bfloat16* al = Alo + (size_t)(m0 + i) * D_;
        const __nv_bfloat16* bh = Bhi + (size_t)(n0 + j) * D_;
        const __nv_bfloat16* bl = Blo + (size_t)(n0 + j) * D_;
        float acc = 0.f;
        for (int k = 0; k < D_; k++) {
            const float a = __bfloat162float(ah[k]) + __bfloat162float(al[k]);
            const float w = __bfloat162float(bh[k]) + __bfloat162float(bl[k]);
            acc = fmaf(a, w, acc);
        }
        C[(size_t)(m0 + i) * D_ + n0 + j] = acc + bias[n0 + j];
    }
#endif
}

// ---------------- fp32 -> bf16 hi/lo split ----------------------------------
__global__ __launch_bounds__(256) void split4(const float* __restrict__ xin, int mode)
{
    const float* in = (mode == 0) ? xin : g_attn;
    __nv_bfloat16* hi = (mode == 0) ? g_xhi : g_ahi;
    __nv_bfloat16* lo = (mode == 0) ? g_xlo : g_alo;
    const int i = (blockIdx.x * 256 + threadIdx.x) << 2;
    float4 v = *(const float4*)(in + i);
    __nv_bfloat16 h0 = __float2bfloat16_rn(v.x);
    __nv_bfloat16 h1 = __float2bfloat16_rn(v.y);
    __nv_bfloat16 h2 = __float2bfloat16_rn(v.z);
    __nv_bfloat16 h3 = __float2bfloat16_rn(v.w);
    __nv_bfloat16 l0 = __float2bfloat16_rn(v.x - __bfloat162float(h0));
    __nv_bfloat16 l1 = __float2bfloat16_rn(v.y - __bfloat162float(h1));
    __nv_bfloat16 l2 = __float2bfloat16_rn(v.z - __bfloat162float(h2));
    __nv_bfloat16 l3 = __float2bfloat16_rn(v.w - __bfloat162float(h3));
    *((__nv_bfloat162*)(hi + i))     = __halves2bfloat162(h0, h1);
    *((__nv_bfloat162*)(hi + i + 2)) = __halves2bfloat162(h2, h3);
    *((__nv_bfloat162*)(lo + i))     = __halves2bfloat162(l0, l1);
    *((__nv_bfloat162*)(lo + i + 2)) = __halves2bfloat162(l2, l3);
}

// ---------------- W [k][n] -> W^T [n][k] bf16 hi/lo -------------------------
__global__ __launch_bounds__(256) void trans_split(
    const float* __restrict__ W0, const float* __restrict__ W1,
    const float* __restrict__ W2, const float* __restrict__ W3)
{
    const int z = blockIdx.z;
    const float* W = (z == 0) ? W0 : (z == 1) ? W1 : (z == 2) ? W2 : W3;
    __nv_bfloat16* Hi = g_wthi[z];
    __nv_bfloat16* Lo = g_wtlo[z];
    __shared__ float t[32][33];
    const int n0 = blockIdx.x << 5, k0 = blockIdx.y << 5;
    const int tx = threadIdx.x, ty = threadIdx.y;
#pragma unroll
    for (int i = 0; i < 4; i++)
        t[ty + 8 * i][tx] = W[(size_t)(k0 + ty + 8 * i) * D_ + n0 + tx];
    __syncthreads();
#pragma unroll
    for (int i = 0; i < 4; i++) {
        const float v = t[tx][ty + 8 * i];
        __nv_bfloat16 h = __float2bfloat16_rn(v);
        __nv_bfloat16 l = __float2bfloat16_rn(v - __bfloat162float(h));
        const size_t o = (size_t)(n0 + ty + 8 * i) * D_ + k0 + tx;
        Hi[o] = h; Lo[o] = l;
    }
}

// ---------------- windowed decay attention (fp32 SIMT) ----------------------
struct AttnSmem {
    float Qs[64][65];
    float Ks[64][65];
    float Vs[64][65];
    float Ss[64][65];
    float tbl[TBL_N];
};

__global__ __launch_bounds__(256) void attn_kernel()
{
    AttnSmem* sm = (AttnSmem*)sm_raw;
    const int tid = threadIdx.x;
    const int qt = blockIdx.x;
    const int bh = blockIdx.y;
    const int b = bh >> 4, h = bh & 15;

    for (int d = tid; d < TBL_N; d += 256)
        sm->tbl[d] = exp2f((float)d * -0.07400058144377693f);

    const int lrow = tid >> 4;
    const int lcol = (tid & 15) << 2;

    const float* qg = g_q + ((b * S_ + (qt << 6)) * D_) + (h << 6);
#pragma unroll
    for (int r = 0; r < 4; r++) {
        const int row = lrow + (r << 4);
        float4 v = *(const float4*)(qg + row * D_ + lcol);
        sm->Qs[row][lcol + 0] = v.x;
        sm->Qs[row][lcol + 1] = v.y;
        sm->Qs[row][lcol + 2] = v.z;
        sm->Qs[row][lcol + 3] = v.w;
    }

    const int tx = tid & 15, ty = tid >> 4;
    float O[4][4];
#pragma unroll
    for (int i = 0; i < 4; i++)
#pragma unroll
        for (int j = 0; j < 4; j++) O[i][j] = 0.f;

    int jt0 = qt - WIN_TILES; if (jt0 < 0) jt0 = 0;
    __syncthreads();

    for (int jt = jt0; jt <= qt; jt++) {
        const float* kg = g_k + ((b * S_ + (jt << 6)) * D_) + (h << 6);
        const float* vg = g_v + ((b * S_ + (jt << 6)) * D_) + (h << 6);
#pragma unroll
        for (int r = 0; r < 4; r++) {
            const int row = lrow + (r << 4);
            float4 kv4 = *(const float4*)(kg + row * D_ + lcol);
            sm->Ks[row][lcol + 0] = kv4.x;
            sm->Ks[row][lcol + 1] = kv4.y;
            sm->Ks[row][lcol + 2] = kv4.z;
            sm->Ks[row][lcol + 3] = kv4.w;
            float4 vv4 = *(const float4*)(vg + row * D_ + lcol);
            sm->Vs[row][lcol + 0] = vv4.x;
            sm->Vs[row][lcol + 1] = vv4.y;
            sm->Vs[row][lcol + 2] = vv4.z;
            sm->Vs[row][lcol + 3] = vv4.w;
        }
        __syncthreads();

        float s[4][4];
#pragma unroll
        for (int i = 0; i < 4; i++)
#pragma unroll
            for (int j = 0; j < 4; j++) s[i][j] = 0.f;

#pragma unroll 8
        for (int d = 0; d < 64; d++) {
            float qv[4], kv[4];
#pragma unroll
            for (int i = 0; i < 4; i++) qv[i] = sm->Qs[ty * 4 + i][d];
#pragma unroll
            for (int j = 0; j < 4; j++) kv[j] = sm->Ks[tx + 16 * j][d];
#pragma unroll
            for (int i = 0; i < 4; i++)
#pragma unroll
                for (int j = 0; j < 4; j++)
                    s[i][j] = fmaf(qv[i], kv[j], s[i][j]);
        }

        const int dbase = ((qt - jt) << 6) + ty * 4 - tx;
#pragma unroll
        for (int i = 0; i < 4; i++)
#pragma unroll
            for (int j = 0; j < 4; j++) {
                const int diff = dbase + i - 16 * j;
                const float f = (diff >= 0) ? sm->tbl[diff] : 0.f;
                sm->Ss[ty * 4 + i][tx + 16 * j] = s[i][j] * f;
            }
        __syncthreads();

#pragma unroll 8
        for (int kk = 0; kk < 64; kk++) {
            float sv[4], vv[4];
#pragma unroll
            for (int i = 0; i < 4; i++) sv[i] = sm->Ss[ty * 4 + i][kk];
#pragma unroll
            for (int j = 0; j < 4; j++) vv[j] = sm->Vs[kk][tx + 16 * j];
#pragma unroll
            for (int i = 0; i < 4; i++)
#pragma unroll
                for (int j = 0; j < 4; j++)
                    O[i][j] = fmaf(sv[i], vv[j], O[i][j]);
        }
        __syncthreads();
    }

    float* og = g_attn + ((b * S_ + (qt << 6)) * D_) + (h << 6);
#pragma unroll
    for (int i = 0; i < 4; i++)
#pragma unroll
        for (int j = 0; j < 4; j++)
            og[(ty * 4 + i) * D_ + tx + 16 * j] = O[i][j];
}

// ---------------- GroupNorm --------------------------------------------------
__global__ __launch_bounds__(256) void gn_partial()
{
    const int c = blockIdx.x;
    const int g = blockIdx.y;
    const int b = g >> 4, h = g & 15;
    const float* base = g_proj + ((b * S_ + (c << 6)) * D_) + (h << 6);
    const int lrow = threadIdx.x >> 4;
    const int lcol = (threadIdx.x & 15) << 2;

    float sum = 0.f, sq = 0.f;
#pragma unroll
    for (int r = 0; r < 4; r++) {
        float4 v = *(const float4*)(base + (lrow + (r << 4)) * D_ + lcol);
        sum += v.x + v.y + v.z + v.w;
        sq  += v.x * v.x + v.y * v.y + v.z * v.z + v.w * v.w;
    }
#pragma unroll
    for (int o = 16; o; o >>= 1) {
        sum += __shfl_down_sync(0xffffffffu, sum, o);
        sq  += __shfl_down_sync(0xffffffffu, sq,  o);
    }
    __shared__ float wsum[8], wsq[8];
    const int wid = threadIdx.x >> 5, lid = threadIdx.x & 31;
    if (lid == 0) { wsum[wid] = sum; wsq[wid] = sq; }
    __syncthreads();
    if (threadIdx.x == 0) {
        float ts = 0.f, tq = 0.f;
#pragma unroll
        for (int w = 0; w < 8; w++) { ts += wsum[w]; tq += wsq[w]; }
        g_part[g * 32 + c] = make_float2(ts, tq);
    }
}

__global__ void gn_stats()
{
    const int g = threadIdx.x;
    float s = 0.f, q = 0.f;
    for (int c = 0; c < 32; c++) {
        float2 p = g_part[g * 32 + c];
        s += p.x; q += p.y;
    }
    const float n = (float)(S_ * HD_);
    const float mu = s / n;
    const float var = q / n - mu * mu;
    g_stats[g] = make_float2(mu, rsqrtf(var + 1e-5f));
}

__global__ __launch_bounds__(256) void gn_apply(
    const float* __restrict__ gamma, const float* __restrict__ beta,
    float* __restrict__ out)
{
    const int t = blockIdx.x * 256 + threadIdx.x;
    const int base = t << 2;
    const int d = base & (D_ - 1);
    const int row = base >> 10;
    const int b = row >> 11;
    const float2 st = g_stats[(b << 4) | (d >> 6)];
    const float4 v  = *(const float4*)(g_proj + base);
    const float4 gm = *(const float4*)(gamma + d);
    const float4 bt = *(const float4*)(beta + d);
    float4 o;
    o.x = (v.x - st.x) * st.y * gm.x + bt.x;
    o.y = (v.y - st.x) * st.y * gm.y + bt.y;
    o.z = (v.z - st.x) * st.y * gm.z + bt.z;
    o.w = (v.w - st.x) * st.y * gm.w + bt.w;
    *(float4*)(out + base) = o;
}

// ---------------- launch ----------------------------------------------------
extern "C" void kernel_launch(void* const* d_in, const int* in_sizes, int n_in,
                              void* d_out, int out_size)
{
    (void)in_sizes; (void)n_in; (void)out_size;
    const float* x     = (const float*)d_in[0];
    const float* Wq    = (const float*)d_in[1];
    const float* bq    = (const float*)d_in[2];
    const float* Wk    = (const float*)d_in[3];
    const float* bk    = (const float*)d_in[4];
    const float* Wv    = (const float*)d_in[5];
    const float* bv    = (const float*)d_in[6];
    const float* Wo    = (const float*)d_in[7];
    const float* bo    = (const float*)d_in[8];
    const float* gamma = (const float*)d_in[9];
    const float* beta  = (const float*)d_in[10];
    float* out = (float*)d_out;

    cudaFuncSetAttribute(attn_kernel,
                         cudaFuncAttributeMaxDynamicSharedMemorySize,
                         (int)sizeof(AttnSmem));
    cudaFuncSetAttribute(gemm_tc,
                         cudaFuncAttributeMaxDynamicSharedMemorySize,
                         DYN_SMEM);

    split4<<<4096, 256>>>(x, 0);
    trans_split<<<dim3(32, 32, 4), dim3(32, 8)>>>(Wq, Wk, Wv, Wo);
    gemm_tc<<<dim3(4, 32, 3), 160, DYN_SMEM>>>(0, bq, bk, bv, bo);
    attn_kernel<<<dim3(32, 32), 256, sizeof(AttnSmem)>>>();
    split4<<<4096, 256>>>(nullptr, 1);
    gemm_tc<<<dim3(4, 32, 1), 160, DYN_SMEM>>>(1, bq, bk, bv, bo);
    gn_partial<<<dim3(32, 32), 256>>>();
    gn_stats<<<1, 32>>>();
    gn_apply<<<(M_ * D_) / (256 * 4), 256>>>(gamma, beta, out);
}

// round 4
// speedup vs baseline: 4.6238x; 1.5300x over previous
#include <cuda_runtime.h>
#include <cuda_bf16.h>
#include <cstdint>

#define B_  2
#define S_  2048
#define D_  1024
#define H_  16
#define HD_ 64
#define M_  (B_ * S_)          // 4096 rows

#define WIN_TILES 6            // 384-key decay window: 0.95^384 ~ 3e-9
#define LOG2DECAY -0.07400058144377693f

// ---------------- scratch (device globals: no allocation allowed) ----------
__device__ float  g_v[M_ * D_];
__device__ float  g_proj[M_ * D_];
__device__ float2 g_part[32 * 32];
__device__ float2 g_stats[32];

__device__ __align__(128) __nv_bfloat16 g_xhi[M_ * D_];
__device__ __align__(128) __nv_bfloat16 g_xlo[M_ * D_];
__device__ __align__(128) __nv_bfloat16 g_qhi[M_ * D_];
__device__ __align__(128) __nv_bfloat16 g_qlo[M_ * D_];
__device__ __align__(128) __nv_bfloat16 g_khi[M_ * D_];
__device__ __align__(128) __nv_bfloat16 g_klo[M_ * D_];
__device__ __align__(128) __nv_bfloat16 g_vthi[B_ * H_ * HD_ * S_];  // [bh][d][t]
__device__ __align__(128) __nv_bfloat16 g_vtlo[B_ * H_ * HD_ * S_];
__device__ __align__(128) __nv_bfloat16 g_ahi[M_ * D_];
__device__ __align__(128) __nv_bfloat16 g_alo[M_ * D_];
__device__ __align__(128) __nv_bfloat16 g_wthi[4][D_ * D_];   // W^T [n][k]
__device__ __align__(128) __nv_bfloat16 g_wtlo[4][D_ * D_];

extern __shared__ unsigned char sm_raw[];

// ---------------- PTX helpers ----------------------------------------------
__device__ __forceinline__ unsigned smem_u32(const void* p) {
    unsigned r;
    asm("{ .reg .u64 t; cvta.to.shared.u64 t, %1; cvt.u32.u64 %0, t; }"
        : "=r"(r) : "l"(p));
    return r;
}

#define MBARRIER_INIT(addr, cnt) \
    asm volatile("mbarrier.init.shared.b64 [%0], %1;" :: "r"(addr), "r"(cnt) : "memory")

#define MBARRIER_WAIT_PARITY(addr, ph) do {                                     \
    unsigned _m = (addr), _p = (ph), _d;                                        \
    asm volatile("{\n\t.reg .pred p;\n\t"                                       \
        "mbarrier.try_wait.parity.acquire.cta.shared::cta.b64 p, [%1], %2;\n\t" \
        "selp.b32 %0, 1, 0, p;\n\t}"                                            \
        : "=r"(_d) : "r"(_m), "r"(_p) : "memory");                              \
    if (!_d) {                                                                  \
        asm volatile("{\n\t.reg .pred P1;\n\t"                                  \
            "WL_%=:\n\t"                                                        \
            "mbarrier.try_wait.parity.acquire.cta.shared::cta.b64 P1, [%0], %1, 0x989680;\n\t" \
            "@P1 bra.uni WD_%=;\n\t"                                            \
            "bra.uni WL_%=;\n\t"                                                \
            "WD_%=:\n\t}"                                                       \
            :: "r"(_m), "r"(_p) : "memory");                                    \
    }                                                                           \
} while (0)

#define CP_ASYNC16(dst, src) \
    asm volatile("cp.async.cg.shared.global [%0], [%1], 16;" :: "r"(dst), "l"(src))
#define CP_COMMIT() asm volatile("cp.async.commit_group;" ::: "memory")
#define CP_WAIT0()  asm volatile("cp.async.wait_group 0;" ::: "memory")
#define FENCE_PROXY_ASYNC() asm volatile("fence.proxy.async.shared::cta;" ::: "memory")
#define BAR1_160() asm volatile("bar.sync 1, 160;" ::: "memory")

#define SWZ(o) ((o) ^ (((o) >> 3) & 0x70))

__device__ __forceinline__ void split_store2(
    __nv_bfloat16* hi, __nv_bfloat16* lo, size_t idx, float v0, float v1)
{
    __nv_bfloat16 h0 = __float2bfloat16_rn(v0);
    __nv_bfloat16 h1 = __float2bfloat16_rn(v1);
    __nv_bfloat16 l0 = __float2bfloat16_rn(v0 - __bfloat162float(h0));
    __nv_bfloat16 l1 = __float2bfloat16_rn(v1 - __bfloat162float(h1));
    *(__nv_bfloat162*)(hi + idx) = __halves2bfloat162(h0, h1);
    *(__nv_bfloat162*)(lo + idx) = __halves2bfloat162(l0, l1);
}

#if defined(__CUDA_ARCH_FEAT_SM103_ALL)

#define TCGEN05_ALLOC(saddr, n) \
    asm volatile("tcgen05.alloc.cta_group::1.sync.aligned.shared::cta.b32 [%0], %1;" \
                 :: "r"(saddr), "r"(n) : "memory")
#define TCGEN05_DEALLOC(t, n) \
    asm volatile("tcgen05.dealloc.cta_group::1.sync.aligned.b32 %0, %1;" :: "r"(t), "r"(n))
#define TCGEN05_RELINQ() \
    asm volatile("tcgen05.relinquish_alloc_permit.cta_group::1.sync.aligned;")
#define TCGEN05_COMMIT(bar) \
    asm volatile("tcgen05.commit.cta_group::1.mbarrier::arrive::one.shared::cluster.b64 [%0];" \
                 :: "r"(bar) : "memory")
#define TCGEN05_FENCE_AFTER() \
    asm volatile("tcgen05.fence::after_thread_sync;" ::: "memory")
#define TCGEN05_FENCE_BEFORE() \
    asm volatile("tcgen05.fence::before_thread_sync;" ::: "memory")
#define TCGEN05_WAIT_LD() \
    asm volatile("tcgen05.wait::ld.sync.aligned;" ::: "memory")

#define TCGEN05_LD_32X32B_X32(r, tmem_addr) \
    asm volatile( \
        "tcgen05.ld.sync.aligned.32x32b.x32.b32 " \
        "{%0, %1, %2, %3, %4, %5, %6, %7, " \
        " %8, %9, %10, %11, %12, %13, %14, %15, " \
        " %16, %17, %18, %19, %20, %21, %22, %23, " \
        " %24, %25, %26, %27, %28, %29, %30, %31}, [%32];" \
        : "=r"((r)[0]),  "=r"((r)[1]),  "=r"((r)[2]),  "=r"((r)[3]), \
          "=r"((r)[4]),  "=r"((r)[5]),  "=r"((r)[6]),  "=r"((r)[7]), \
          "=r"((r)[8]),  "=r"((r)[9]),  "=r"((r)[10]), "=r"((r)[11]), \
          "=r"((r)[12]), "=r"((r)[13]), "=r"((r)[14]), "=r"((r)[15]), \
          "=r"((r)[16]), "=r"((r)[17]), "=r"((r)[18]), "=r"((r)[19]), \
          "=r"((r)[20]), "=r"((r)[21]), "=r"((r)[22]), "=r"((r)[23]), \
          "=r"((r)[24]), "=r"((r)[25]), "=r"((r)[26]), "=r"((r)[27]), \
          "=r"((r)[28]), "=r"((r)[29]), "=r"((r)[30]), "=r"((r)[31]) \
        : "r"(tmem_addr))

__device__ __forceinline__ void mma_f16_ss(
    unsigned d_tmem, unsigned long long a_desc, unsigned long long b_desc,
    unsigned idesc, unsigned enable)
{
    asm volatile(
        "{\n\t.reg .pred p;\n\t"
        "setp.ne.u32 p, %4, 0;\n\t"
        "tcgen05.mma.cta_group::1.kind::f16 [%0], %1, %2, %3, {%5, %5, %5, %5}, p;\n\t"
        "}"
        :: "r"(d_tmem), "l"(a_desc), "l"(b_desc), "r"(idesc), "r"(enable), "r"(0u)
        : "memory");
}

__device__ __forceinline__ unsigned long long sdesc(unsigned addr) {
    // SW128, Blackwell version=1, LBO=1, SBO=64
    return 0x4000404000010000ull | ((unsigned long long)(addr >> 4) & 0x3FFF);
}

#endif  // __CUDA_ARCH_FEAT_SM103_ALL

// ---------------- tcgen05 split-bf16 GEMM: C[4096x1024] = A*W^T + bias -----
#define GEMM_IDESC 0x08400490u   // F32 acc, bf16 a/b, N=256, M=128
#define STAGE_BYTES 98304
#define DYN_SMEM (2048 + 2 * STAGE_BYTES)

__device__ __forceinline__ void load_tile(
    unsigned dst_base, const __nv_bfloat16* gsrc, int row0, int kb, int nrows, int t)
{
    const char* src0 = (const char*)gsrc + ((size_t)row0 * D_ + kb) * 2;
    const int ng = nrows * 8;
    for (int g = t; g < ng; g += 128) {
        const int row = g >> 3, c = g & 7;
        unsigned dst = dst_base + SWZ(row * 128 + c * 16);
        CP_ASYNC16(dst, src0 + (size_t)row * (D_ * 2) + c * 16);
    }
}

__global__ __launch_bounds__(160, 1) void gemm_tc(
    int mode,
    const float* __restrict__ bq, const float* __restrict__ bk,
    const float* __restrict__ bv, const float* __restrict__ bo)
{
    const int tid = threadIdx.x;
    const int n0 = blockIdx.x << 8;     // 0..768
    const int m0 = blockIdx.y << 7;     // 0..3968
    const int z = blockIdx.z;

    const __nv_bfloat16 *Ahi, *Alo, *Bhi, *Blo;
    const float* bias;
    float* C = nullptr;
    __nv_bfloat16 *Chi = nullptr, *Clo = nullptr;
    int splitOut;
    if (mode == 0) {
        Ahi = g_xhi; Alo = g_xlo;
        Bhi = g_wthi[z]; Blo = g_wtlo[z];
        bias = (z == 0) ? bq : (z == 1) ? bk : bv;
        if (z == 0)      { Chi = g_qhi; Clo = g_qlo; splitOut = 1; }
        else if (z == 1) { Chi = g_khi; Clo = g_klo; splitOut = 1; }
        else             { C = g_v; splitOut = 0; }
    } else {
        Ahi = g_ahi; Alo = g_alo;
        Bhi = g_wthi[3]; Blo = g_wtlo[3];
        bias = bo; C = g_proj; splitOut = 0;
    }

#if defined(__CUDA_ARCH_FEAT_SM103_ALL)
    const unsigned sb = smem_u32(sm_raw);
    const int warp = tid >> 5, lane = tid & 31;

    if (tid == 0) {
        MBARRIER_INIT(sb + 0, 1);
        MBARRIER_INIT(sb + 8, 1);
        MBARRIER_INIT(sb + 16, 1);
    }
    if (warp == 4) {
        TCGEN05_ALLOC(sb + 64, 256);
        TCGEN05_RELINQ();
    }
    if (tid < 128) {
        float* sbias = (float*)(sm_raw + 1024);
        sbias[tid] = bias[n0 + tid];
        sbias[tid + 128] = bias[n0 + 128 + tid];
    }
    __syncthreads();

    unsigned tmem;
    asm volatile("ld.shared.b32 %0, [%1];" : "=r"(tmem) : "r"(sb + 64));

    if (warp < 4) {
        for (int c = 0; c < 16; c++) {
            const int s = c & 1, u = c >> 1;
            const unsigned ph = (unsigned)((u & 1) ^ 1);
            MBARRIER_WAIT_PARITY(sb + s * 8, ph);
            const unsigned st = sb + 2048 + s * STAGE_BYTES;
            const int kb = c << 6;
            load_tile(st +     0, Ahi, m0, kb, 128, tid);
            load_tile(st + 16384, Alo, m0, kb, 128, tid);
            load_tile(st + 32768, Bhi, n0, kb, 256, tid);
            load_tile(st + 65536, Blo, n0, kb, 256, tid);
            CP_COMMIT();
            CP_WAIT0();
            FENCE_PROXY_ASYNC();
            BAR1_160();
        }
        MBARRIER_WAIT_PARITY(sb + 16, 0);
        TCGEN05_FENCE_AFTER();
        const float* sbias = (const float*)(sm_raw + 1024);
        const size_t rb = (size_t)(m0 + warp * 32 + lane) * D_ + n0;
        for (int cb = 0; cb < 8; cb++) {
            unsigned r[32];
            TCGEN05_LD_32X32B_X32(r, tmem + cb * 32);
            TCGEN05_WAIT_LD();
            if (splitOut) {
#pragma unroll
                for (int j = 0; j < 32; j += 2) {
                    const float v0 = __uint_as_float(r[j + 0]) + sbias[cb * 32 + j + 0];
                    const float v1 = __uint_as_float(r[j + 1]) + sbias[cb * 32 + j + 1];
                    split_store2(Chi, Clo, rb + cb * 32 + j, v0, v1);
                }
            } else {
#pragma unroll
                for (int j = 0; j < 32; j += 4) {
                    float4 o;
                    o.x = __uint_as_float(r[j + 0]) + sbias[cb * 32 + j + 0];
                    o.y = __uint_as_float(r[j + 1]) + sbias[cb * 32 + j + 1];
                    o.z = __uint_as_float(r[j + 2]) + sbias[cb * 32 + j + 2];
                    o.w = __uint_as_float(r[j + 3]) + sbias[cb * 32 + j + 3];
                    *(float4*)(C + rb + cb * 32 + j) = o;
                }
            }
        }
        TCGEN05_FENCE_BEFORE();
    } else {
        for (int c = 0; c < 16; c++) {
            BAR1_160();
            if (lane == 0) {
                const int s = c & 1;
                const unsigned st = sb + 2048 + s * STAGE_BYTES;
                const unsigned long long dahi = sdesc(st);
                const unsigned long long dalo = sdesc(st + 16384);
                const unsigned long long dbhi = sdesc(st + 32768);
                const unsigned long long dblo = sdesc(st + 65536);
#pragma unroll
                for (int k = 0; k < 4; k++) {
                    const unsigned long long off = 2ull * k;
                    mma_f16_ss(tmem, dahi + off, dbhi + off, GEMM_IDESC,
                               (c == 0 && k == 0) ? 0u : 1u);
                    mma_f16_ss(tmem, dahi + off, dblo + off, GEMM_IDESC, 1u);
                    mma_f16_ss(tmem, dalo + off, dbhi + off, GEMM_IDESC, 1u);
                }
                TCGEN05_COMMIT(sb + s * 8);
            }
        }
        if (lane == 0) TCGEN05_COMMIT(sb + 16);
    }
    __syncthreads();
    if (warp == 4) TCGEN05_DEALLOC(tmem, 256);
#else
    for (int idx = tid; idx < 128 * 256; idx += 160) {
        const int i = idx >> 8, j = idx & 255;
        const __nv_bfloat16* ah = Ahi + (size_t)(m0 + i) * D_;
        const __nv_bfloat16* al = Alo + (size_t)(m0 + i) * D_;
        const __nv_bfloat16* bh = Bhi + (size_t)(n0 + j) * D_;
        const __nv_bfloat16* bl = Blo + (size_t)(n0 + j) * D_;
        float acc = 0.f;
        for (int k = 0; k < D_; k++) {
            const float a = __bfloat162float(ah[k]) + __bfloat162float(al[k]);
            const float w = __bfloat162float(bh[k]) + __bfloat162float(bl[k]);
            acc = fmaf(a, w, acc);
        }
        const float v = acc + bias[n0 + j];
        const size_t o = (size_t)(m0 + i) * D_ + n0 + j;
        if (splitOut) {
            __nv_bfloat16 h = __float2bfloat16_rn(v);
            Chi[o] = h;
            Clo[o] = __float2bfloat16_rn(v - __bfloat162float(h));
        } else {
            C[o] = v;
        }
    }
#endif
}

// ---------------- fp32 -> bf16 hi/lo split (x) -------------------------------
__global__ __launch_bounds__(256) void split4(const float* __restrict__ in)
{
    const int i = (blockIdx.x * 256 + threadIdx.x) << 2;
    float4 v = *(const float4*)(in + i);
    split_store2(g_xhi, g_xlo, i, v.x, v.y);
    split_store2(g_xhi, g_xlo, i + 2, v.z, v.w);
}

// ---------------- W [k][n] -> W^T [n][k] bf16 hi/lo -------------------------
__global__ __launch_bounds__(256) void trans_split(
    const float* __restrict__ W0, const float* __restrict__ W1,
    const float* __restrict__ W2, const float* __restrict__ W3)
{
    const int z = blockIdx.z;
    const float* W = (z == 0) ? W0 : (z == 1) ? W1 : (z == 2) ? W2 : W3;
    __nv_bfloat16* Hi = g_wthi[z];
    __nv_bfloat16* Lo = g_wtlo[z];
    __shared__ float t[32][33];
    const int n0 = blockIdx.x << 5, k0 = blockIdx.y << 5;
    const int tx = threadIdx.x, ty = threadIdx.y;
#pragma unroll
    for (int i = 0; i < 4; i++)
        t[ty + 8 * i][tx] = W[(size_t)(k0 + ty + 8 * i) * D_ + n0 + tx];
    __syncthreads();
#pragma unroll
    for (int i = 0; i < 4; i++) {
        const float v = t[tx][ty + 8 * i];
        __nv_bfloat16 h = __float2bfloat16_rn(v);
        __nv_bfloat16 l = __float2bfloat16_rn(v - __bfloat162float(h));
        const size_t o = (size_t)(n0 + ty + 8 * i) * D_ + k0 + tx;
        Hi[o] = h; Lo[o] = l;
    }
}

// ---------------- V [token][D] fp32 -> V^T [bh][d][token] bf16 hi/lo --------
__global__ __launch_bounds__(256) void vt_split()
{
    __shared__ float t[32][33];
    const int bh = blockIdx.z;
    const int b = bh >> 4, h = bh & 15;
    const int t0 = blockIdx.x << 5;   // token tile
    const int d0 = blockIdx.y << 5;   // head-dim tile (0 or 32)
    const int tx = threadIdx.x, ty = threadIdx.y;
#pragma unroll
    for (int i = 0; i < 4; i++)
        t[ty + 8 * i][tx] =
            g_v[(size_t)(b * S_ + t0 + ty + 8 * i) * D_ + h * HD_ + d0 + tx];
    __syncthreads();
#pragma unroll
    for (int i = 0; i < 4; i++) {
        const float v = t[tx][ty + 8 * i];
        __nv_bfloat16 hh = __float2bfloat16_rn(v);
        __nv_bfloat16 ll = __float2bfloat16_rn(v - __bfloat162float(hh));
        const size_t o = (size_t)(bh * HD_ + d0 + ty + 8 * i) * S_ + t0 + tx;
        g_vthi[o] = hh; g_vtlo[o] = ll;
    }
}

// ---------------- tcgen05 windowed decay attention ---------------------------
// CTA: 128 q rows x one (b,h). 128 threads.
#define ATT_IDESC 0x08100490u   // F32 acc, bf16, N=64, M=128
#define SO_BAR_S 0
#define SO_BAR_V 8
#define SO_TMEM  16
#define SO_TBL   1024
#define SO_QHI   3072
#define SO_QLO   (SO_QHI + 16384)
#define SO_KHI   (SO_QLO + 16384)
#define SO_KLO   (SO_KHI + 8192)
#define SO_VHI   (SO_KLO + 8192)
#define SO_VLO   (SO_VHI + 8192)
#define SO_SHI   (SO_VLO + 8192)
#define SO_SLO   (SO_SHI + 16384)
#define ATT_SMEM (SO_SLO + 16384)   // 101376 bytes

__global__ __launch_bounds__(128, 2) void attn_tc()
{
    const int tid = threadIdx.x;
    const int qp = blockIdx.x;            // 0..15 (128-row block)
    const int bh = blockIdx.y;            // 0..31
    const int b = bh >> 4, h = bh & 15;
    const int qb = qp << 7;               // local token base
    const int qt0 = qp << 1;
    int jt0 = qt0 - WIN_TILES; if (jt0 < 0) jt0 = 0;
    const int nt = (qt0 + 1) - jt0 + 1;

#if defined(__CUDA_ARCH_FEAT_SM103_ALL)
    const unsigned sb = smem_u32(sm_raw);
    const int warp = tid >> 5, lane = tid & 31;

    if (warp == 0) { TCGEN05_ALLOC(sb + SO_TMEM, 128); TCGEN05_RELINQ(); }
    if (tid == 0) {
        MBARRIER_INIT(sb + SO_BAR_S, 1);
        MBARRIER_INIT(sb + SO_BAR_V, 1);
    }
    float* tbl = (float*)(sm_raw + SO_TBL);
    for (int d = tid; d < 512; d += 128)
        tbl[d] = exp2f((float)d * LOG2DECAY);

    // Q tile loads: 128 rows x 128B, hi+lo
    {
        const char* qh = (const char*)(g_qhi + ((size_t)(b * S_ + qb)) * D_ + h * HD_);
        const char* ql = (const char*)(g_qlo + ((size_t)(b * S_ + qb)) * D_ + h * HD_);
        for (int g = tid; g < 1024; g += 128) {
            const int row = g >> 3, c = g & 7;
            const unsigned so = SWZ(row * 128 + c * 16);
            CP_ASYNC16(sb + SO_QHI + so, qh + (size_t)row * (D_ * 2) + c * 16);
            CP_ASYNC16(sb + SO_QLO + so, ql + (size_t)row * (D_ * 2) + c * 16);
        }
    }
    CP_COMMIT(); CP_WAIT0(); FENCE_PROXY_ASYNC();
    __syncthreads();

    unsigned tmem;
    asm volatile("ld.shared.b32 %0, [%1];" : "=r"(tmem) : "r"(sb + SO_TMEM));

    const unsigned long long dQhi = sdesc(sb + SO_QHI), dQlo = sdesc(sb + SO_QLO);
    const unsigned long long dKhi = sdesc(sb + SO_KHI), dKlo = sdesc(sb + SO_KLO);
    const unsigned long long dVhi = sdesc(sb + SO_VHI), dVlo = sdesc(sb + SO_VLO);
    const unsigned long long dShi = sdesc(sb + SO_SHI), dSlo = sdesc(sb + SO_SLO);

    unsigned phs = 0, phv = 0;
    const int qrow = qb + warp * 32 + lane;       // local to batch
    const unsigned rowoff = (unsigned)(warp * 32 + lane) * 128;

    for (int it = 0; it < nt; it++) {
        const int jt = jt0 + it;
        // K/V tile loads: 64 rows x 128B each, hi+lo
        {
            const char* kh = (const char*)(g_khi + ((size_t)(b * S_ + (jt << 6))) * D_ + h * HD_);
            const char* kl = (const char*)(g_klo + ((size_t)(b * S_ + (jt << 6))) * D_ + h * HD_);
            const char* vh = (const char*)(g_vthi + (size_t)bh * HD_ * S_ + (jt << 6));
            const char* vl = (const char*)(g_vtlo + (size_t)bh * HD_ * S_ + (jt << 6));
            for (int g = tid; g < 512; g += 128) {
                const int row = g >> 3, c = g & 7;
                const unsigned so = SWZ(row * 128 + c * 16);
                CP_ASYNC16(sb + SO_KHI + so, kh + (size_t)row * (D_ * 2) + c * 16);
                CP_ASYNC16(sb + SO_KLO + so, kl + (size_t)row * (D_ * 2) + c * 16);
                CP_ASYNC16(sb + SO_VHI + so, vh + (size_t)row * (S_ * 2) + c * 16);
                CP_ASYNC16(sb + SO_VLO + so, vl + (size_t)row * (S_ * 2) + c * 16);
            }
        }
        CP_COMMIT(); CP_WAIT0(); FENCE_PROXY_ASYNC();
        __syncthreads();

        // S = Q K^T
        if (tid == 0) {
#pragma unroll
            for (int k = 0; k < 4; k++) {
                const unsigned long long off = 2ull * k;
                mma_f16_ss(tmem + 64, dQhi + off, dKhi + off, ATT_IDESC, k > 0 ? 1u : 0u);
                mma_f16_ss(tmem + 64, dQhi + off, dKlo + off, ATT_IDESC, 1u);
                mma_f16_ss(tmem + 64, dQlo + off, dKhi + off, ATT_IDESC, 1u);
            }
            TCGEN05_COMMIT(sb + SO_BAR_S);
        }
        MBARRIER_WAIT_PARITY(sb + SO_BAR_S, phs); phs ^= 1;
        TCGEN05_FENCE_AFTER();

        // convert: mask + split + STS
        const int kbase = jt << 6;
#pragma unroll
        for (int half = 0; half < 2; half++) {
            unsigned r[32];
            TCGEN05_LD_32X32B_X32(r, tmem + 64 + half * 32);
            TCGEN05_WAIT_LD();
#pragma unroll
            for (int c = 0; c < 32; c += 2) {
                const int col = half * 32 + c;
                const int d0 = qrow - (kbase + col);
                const int d1 = d0 - 1;
                const float f0 = (d0 >= 0) ? tbl[d0] : 0.f;
                const float f1 = (d1 >= 0) ? tbl[d1] : 0.f;
                const float v0 = __uint_as_float(r[c]) * f0;
                const float v1 = __uint_as_float(r[c + 1]) * f1;
                __nv_bfloat16 h0 = __float2bfloat16_rn(v0);
                __nv_bfloat16 h1 = __float2bfloat16_rn(v1);
                __nv_bfloat16 l0 = __float2bfloat16_rn(v0 - __bfloat162float(h0));
                __nv_bfloat16 l1 = __float2bfloat16_rn(v1 - __bfloat162float(h1));
                const unsigned so = SWZ(rowoff + col * 2);
                *(__nv_bfloat162*)(sm_raw + SO_SHI + so) = __halves2bfloat162(h0, h1);
                *(__nv_bfloat162*)(sm_raw + SO_SLO + so) = __halves2bfloat162(l0, l1);
            }
        }
        FENCE_PROXY_ASYNC();
        __syncthreads();

        // O += S V
        if (tid == 0) {
#pragma unroll
            for (int k = 0; k < 4; k++) {
                const unsigned long long off = 2ull * k;
                mma_f16_ss(tmem, dShi + off, dVhi + off, ATT_IDESC,
                           (it == 0 && k == 0) ? 0u : 1u);
                mma_f16_ss(tmem, dShi + off, dVlo + off, ATT_IDESC, 1u);
                mma_f16_ss(tmem, dSlo + off, dVhi + off, ATT_IDESC, 1u);
            }
            TCGEN05_COMMIT(sb + SO_BAR_V);
        }
        MBARRIER_WAIT_PARITY(sb + SO_BAR_V, phv); phv ^= 1;
        TCGEN05_FENCE_AFTER();
    }

    // epilogue: O -> g_ahi/g_alo (bf16 hi/lo)
    {
        const size_t rb = (size_t)(b * S_ + qrow) * D_ + h * HD_;
#pragma unroll
        for (int half = 0; half < 2; half++) {
            unsigned r[32];
            TCGEN05_LD_32X32B_X32(r, tmem + half * 32);
            TCGEN05_WAIT_LD();
#pragma unroll
            for (int c = 0; c < 32; c += 2)
                split_store2(g_ahi, g_alo, rb + half * 32 + c,
                             __uint_as_float(r[c]), __uint_as_float(r[c + 1]));
        }
        TCGEN05_FENCE_BEFORE();
    }
    __syncthreads();
    if (warp == 0) TCGEN05_DEALLOC(tmem, 128);
#else
    // -------- correct (very slow) fallback: never runs on GB300 -------------
    const int jlo = jt0 << 6;
    for (int e = tid; e < 128 * HD_; e += 128) {
        const int i = e >> 6, d = e & 63;
        const int qr = qb + i;
        float acc = 0.f;
        for (int j = jlo; j <= qr; j++) {
            float s = 0.f;
            const size_t qo = (size_t)(b * S_ + qr) * D_ + h * HD_;
            const size_t ko = (size_t)(b * S_ + j) * D_ + h * HD_;
            for (int k = 0; k < HD_; k++) {
                const float qv = __bfloat162float(g_qhi[qo + k]) + __bfloat162float(g_qlo[qo + k]);
                const float kv = __bfloat162float(g_khi[ko + k]) + __bfloat162float(g_klo[ko + k]);
                s = fmaf(qv, kv, s);
            }
            const float f = exp2f((float)(qr - j) * LOG2DECAY);
            const size_t vo = (size_t)(bh * HD_ + d) * S_ + j;
            const float vv = __bfloat162float(g_vthi[vo]) + __bfloat162float(g_vtlo[vo]);
            acc = fmaf(s * f, vv, acc);
        }
        const size_t o = (size_t)(b * S_ + qr) * D_ + h * HD_ + d;
        __nv_bfloat16 hh = __float2bfloat16_rn(acc);
        g_ahi[o] = hh;
        g_alo[o] = __float2bfloat16_rn(acc - __bfloat162float(hh));
    }
#endif
}

// ---------------- GroupNorm --------------------------------------------------
__global__ __launch_bounds__(256) void gn_partial()
{
    const int c = blockIdx.x;
    const int g = blockIdx.y;
    const int b = g >> 4, h = g & 15;
    const float* base = g_proj + ((b * S_ + (c << 6)) * D_) + (h << 6);
    const int lrow = threadIdx.x >> 4;
    const int lcol = (threadIdx.x & 15) << 2;

    float sum = 0.f, sq = 0.f;
#pragma unroll
    for (int r = 0; r < 4; r++) {
        float4 v = *(const float4*)(base + (lrow + (r << 4)) * D_ + lcol);
        sum += v.x + v.y + v.z + v.w;
        sq  += v.x * v.x + v.y * v.y + v.z * v.z + v.w * v.w;
    }
#pragma unroll
    for (int o = 16; o; o >>= 1) {
        sum += __shfl_down_sync(0xffffffffu, sum, o);
        sq  += __shfl_down_sync(0xffffffffu, sq,  o);
    }
    __shared__ float wsum[8], wsq[8];
    const int wid = threadIdx.x >> 5, lid = threadIdx.x & 31;
    if (lid == 0) { wsum[wid] = sum; wsq[wid] = sq; }
    __syncthreads();
    if (threadIdx.x == 0) {
        float ts = 0.f, tq = 0.f;
#pragma unroll
        for (int w = 0; w < 8; w++) { ts += wsum[w]; tq += wsq[w]; }
        g_part[g * 32 + c] = make_float2(ts, tq);
    }
}

__global__ void gn_stats()
{
    const int g = threadIdx.x;
    float s = 0.f, q = 0.f;
    for (int c = 0; c < 32; c++) {
        float2 p = g_part[g * 32 + c];
        s += p.x; q += p.y;
    }
    const float n = (float)(S_ * HD_);
    const float mu = s / n;
    const float var = q / n - mu * mu;
    g_stats[g] = make_float2(mu, rsqrtf(var + 1e-5f));
}

__global__ __launch_bounds__(256) void gn_apply(
    const float* __restrict__ gamma, const float* __restrict__ beta,
    float* __restrict__ out)
{
    const int t = blockIdx.x * 256 + threadIdx.x;
    const int base = t << 2;
    const int d = base & (D_ - 1);
    const int row = base >> 10;
    const int b = row >> 11;
    const float2 st = g_stats[(b << 4) | (d >> 6)];
    const float4 v  = *(const float4*)(g_proj + base);
    const float4 gm = *(const float4*)(gamma + d);
    const float4 bt = *(const float4*)(beta + d);
    float4 o;
    o.x = (v.x - st.x) * st.y * gm.x + bt.x;
    o.y = (v.y - st.x) * st.y * gm.y + bt.y;
    o.z = (v.z - st.x) * st.y * gm.z + bt.z;
    o.w = (v.w - st.x) * st.y * gm.w + bt.w;
    *(float4*)(out + base) = o;
}

// ---------------- launch ----------------------------------------------------
extern "C" void kernel_launch(void* const* d_in, const int* in_sizes, int n_in,
                              void* d_out, int out_size)
{
    (void)in_sizes; (void)n_in; (void)out_size;
    const float* x     = (const float*)d_in[0];
    const float* Wq    = (const float*)d_in[1];
    const float* bq    = (const float*)d_in[2];
    const float* Wk    = (const float*)d_in[3];
    const float* bk    = (const float*)d_in[4];
    const float* Wv    = (const float*)d_in[5];
    const float* bv    = (const float*)d_in[6];
    const float* Wo    = (const float*)d_in[7];
    const float* bo    = (const float*)d_in[8];
    const float* gamma = (const float*)d_in[9];
    const float* beta  = (const float*)d_in[10];
    float* out = (float*)d_out;

    cudaFuncSetAttribute(gemm_tc,
                         cudaFuncAttributeMaxDynamicSharedMemorySize, DYN_SMEM);
    cudaFuncSetAttribute(attn_tc,
                         cudaFuncAttributeMaxDynamicSharedMemorySize, ATT_SMEM);

    split4<<<4096, 256>>>(x);
    trans_split<<<dim3(32, 32, 4), dim3(32, 8)>>>(Wq, Wk, Wv, Wo);
    gemm_tc<<<dim3(4, 32, 3), 160, DYN_SMEM>>>(0, bq, bk, bv, bo);
    vt_split<<<dim3(64, 2, 32), dim3(32, 8)>>>();
    attn_tc<<<dim3(16, 32), 128, ATT_SMEM>>>();
    gemm_tc<<<dim3(4, 32, 1), 160, DYN_SMEM>>>(1, bq, bk, bv, bo);
    gn_partial<<<dim3(32, 32), 256>>>();
    gn_stats<<<1, 32>>>();
    gn_apply<<<(M_ * D_) / (256 * 4), 256>>>(gamma, beta, out);
}